// round 9
// baseline (speedup 1.0000x reference)
#include <cuda_runtime.h>
#include <cuda_bf16.h>
#include <math.h>
#include <stdint.h>

// ---------------- problem constants ----------------
#define BB 2
#define SQ 1024
#define D_ 2048
#define HN 16
#define HD 128
#define NTOK (BB*SQ)       // 2048
#define EE 8
#define DE_ 704
#define NSLOT (NTOK*2)     // 4096 (top-2 per token)

typedef __nv_bfloat16 bf16;

// ---------------- scratch (device globals: no allocations allowed) ----------------
__device__ float g_q   [NTOK*D_];
__device__ float g_k   [NTOK*D_];
__device__ float g_v   [NTOK*D_];
__device__ float g_h   [NTOK*D_];
__device__ float g_xn2 [NTOK*D_];
__device__ float g_gb  [NSLOT*DE_];
__device__ float g_ub  [NSLOT*DE_];
__device__ float g_op  [NSLOT*D_];
__device__ int   g_cnt [EE];
__device__ int   g_cur [EE];
__device__ int   g_off [EE];
__device__ int   g_tope[NTOK*2];
__device__ float g_topw[NTOK*2];
__device__ int   g_slot_tok[NSLOT];
__device__ float g_slot_w  [NSLOT];
__device__ int   g_tok_pos [NTOK*2];
// bf16 hi/lo planes: activations
__device__ bf16 g_xnh[NTOK*D_],  g_xnl[NTOK*D_];    // pre-attn norm out
__device__ bf16 g_qh [NTOK*D_],  g_ql [NTOK*D_];
__device__ bf16 g_kh [NTOK*D_],  g_kl [NTOK*D_];
__device__ bf16 g_vth[NTOK*D_],  g_vtl[NTOK*D_];    // V transposed [bh][HD][SQ]
__device__ bf16 g_ah [NTOK*D_],  g_al [NTOK*D_];    // attention out
__device__ bf16 g_x2h[NTOK*D_],  g_x2l[NTOK*D_];    // post-attn norm out
__device__ bf16 g_ih [NSLOT*DE_], g_il [NSLOT*DE_]; // swiglu inter
// bf16 hi/lo planes: weights
__device__ bf16 g_wqh[D_*D_], g_wql[D_*D_];
__device__ bf16 g_wkh[D_*D_], g_wkl[D_*D_];
__device__ bf16 g_wvh[D_*D_], g_wvl[D_*D_];
__device__ bf16 g_woh[D_*D_], g_wol[D_*D_];
__device__ bf16 g_egh[EE*DE_*D_], g_egl[EE*DE_*D_];
__device__ bf16 g_euh[EE*DE_*D_], g_eul[EE*DE_*D_];
__device__ bf16 g_edh[EE*D_*DE_], g_edl[EE*D_*DE_];

// ---------------- helpers ----------------
__device__ __forceinline__ uint32_t smem_u32(const void* p) {
    uint32_t a;
    asm("{ .reg .u64 t; cvta.to.shared.u64 t, %1; cvt.u32.u64 %0, t; }" : "=r"(a) : "l"(p));
    return a;
}
__device__ __forceinline__ void mma_bf16(float* c, const uint32_t* a,
                                         uint32_t b0, uint32_t b1) {
    asm volatile(
        "mma.sync.aligned.m16n8k16.row.col.f32.bf16.bf16.f32 "
        "{%0,%1,%2,%3}, {%4,%5,%6,%7}, {%8,%9}, {%0,%1,%2,%3};"
        : "+f"(c[0]), "+f"(c[1]), "+f"(c[2]), "+f"(c[3])
        : "r"(a[0]), "r"(a[1]), "r"(a[2]), "r"(a[3]), "r"(b0), "r"(b1));
}
__device__ __forceinline__ void split2(float x0, float x1, uint32_t& wh, uint32_t& wl) {
    bf16 h0 = __float2bfloat16(x0);
    bf16 h1 = __float2bfloat16(x1);
    bf16 l0 = __float2bfloat16(x0 - __bfloat162float(h0));
    bf16 l1 = __float2bfloat16(x1 - __bfloat162float(h1));
    wh = ((uint32_t)__bfloat16_as_ushort(h1) << 16) | __bfloat16_as_ushort(h0);
    wl = ((uint32_t)__bfloat16_as_ushort(l1) << 16) | __bfloat16_as_ushort(l0);
}
__device__ __forceinline__ void split1(float x, bf16& h, bf16& l) {
    h = __float2bfloat16(x);
    l = __float2bfloat16(x - __bfloat162float(h));
}
__device__ __forceinline__ void cpa16(uint32_t dst, const void* src, int szbytes) {
    asm volatile("cp.async.ca.shared.global [%0], [%1], 16, %2;"
                 :: "r"(dst), "l"(src), "r"(szbytes));
}
#define CP_COMMIT() asm volatile("cp.async.commit_group;" ::: "memory")
#define CP_WAIT2()  asm volatile("cp.async.wait_group 2;" ::: "memory")

// ---------------- cp.async 3-stage bf16x3 GEMM ----------------
// C[M,N] = A[M,K] * W[N,K]^T (+add), A/W given as bf16 hi/lo planes.
// MODE 0: dense. MODE 1: A rows gathered via g_slot_tok. MODE 2: A rows contiguous slots.
#define TM 128
#define TN 128
#define BK 16
#define STG_B 24576            // bytes per stage: 4 tiles x 128 rows x 48B
#define GSMEM (3*STG_B)

template<int MODE>
__global__ void __launch_bounds__(256) gemm_bf3(
    const bf16* __restrict__ AH, const bf16* __restrict__ AL,
    const bf16* __restrict__ WH, const bf16* __restrict__ WL,
    float* __restrict__ C, const float* __restrict__ addp,
    int M, int Nn, int Kk, long wstride)
{
    extern __shared__ __align__(16) uint8_t smem_raw[];
    uint32_t sb = smem_u32(smem_raw);

    int e = blockIdx.z;
    int Mloc = M, base = 0;
    const bf16* WHp = WH; const bf16* WLp = WL;
    if (MODE != 0) {
        Mloc = g_cnt[e]; base = g_off[e];
        WHp = WH + (size_t)e * (size_t)wstride;
        WLp = WL + (size_t)e * (size_t)wstride;
    }
    int m0 = blockIdx.y * TM;
    if (m0 >= Mloc) return;
    int n0 = blockIdx.x * TN;
    int tid = threadIdx.x;

    // staging: thread t -> row = t>>1 (0..127), half = t&1 (16B chunk)
    int srow = tid >> 1, half = tid & 1;
    uint32_t dOff = (uint32_t)(srow * 48 + half * 16);
    int gm = m0 + srow;
    bool av = gm < Mloc;
    int arow;
    if (MODE == 0)      arow = av ? gm : 0;
    else if (MODE == 1) arow = av ? g_slot_tok[base + gm] : 0;
    else                arow = av ? (base + gm) : 0;
    const bf16* pAh = AH + (size_t)arow * Kk + half * 8;
    const bf16* pAl = AL + (size_t)arow * Kk + half * 8;
    int asz = av ? 16 : 0;
    int gn = n0 + srow;
    bool bv = gn < Nn;
    const bf16* pBh = WHp + (size_t)(bv ? gn : 0) * Kk + half * 8;
    const bf16* pBl = WLp + (size_t)(bv ? gn : 0) * Kk + half * 8;
    int bsz = bv ? 16 : 0;

    int lane = tid & 31, g = lane >> 2, tg = lane & 3;
    int wm = (tid >> 5) & 3;
    int wn = tid >> 7;
    int mbase = wm * 32, nbase = wn * 64;

    float acc[2][8][4];
#pragma unroll
    for (int mt = 0; mt < 2; mt++)
#pragma unroll
        for (int nt = 0; nt < 8; nt++)
#pragma unroll
            for (int q = 0; q < 4; q++) acc[mt][nt][q] = 0.f;

    int nk = Kk / BK;

    // prologue: fill 3 stages
#pragma unroll
    for (int s = 0; s < 3; s++) {
        if (s < nk) {
            uint32_t st = sb + s * STG_B;
            int k0 = s * BK;
            cpa16(st + dOff,         pAh + k0, asz);
            cpa16(st + 6144 + dOff,  pAl + k0, asz);
            cpa16(st + 12288 + dOff, pBh + k0, bsz);
            cpa16(st + 18432 + dOff, pBl + k0, bsz);
        }
        CP_COMMIT();
    }

    int buf = 0;
    for (int it = 0; it < nk; it++) {
        CP_WAIT2();
        __syncthreads();

        const uint32_t* AhW = (const uint32_t*)(smem_raw + buf * STG_B);
        const uint32_t* AlW = (const uint32_t*)(smem_raw + buf * STG_B + 6144);
        const uint32_t* BhW = (const uint32_t*)(smem_raw + buf * STG_B + 12288);
        const uint32_t* BlW = (const uint32_t*)(smem_raw + buf * STG_B + 18432);

        uint32_t ah[2][4], al[2][4];
#pragma unroll
        for (int mt = 0; mt < 2; mt++) {
            int r0 = (mbase + mt * 16 + g) * 12;
            int r1 = r0 + 8 * 12;
            ah[mt][0] = AhW[r0 + tg];     ah[mt][1] = AhW[r1 + tg];
            ah[mt][2] = AhW[r0 + tg + 4]; ah[mt][3] = AhW[r1 + tg + 4];
            al[mt][0] = AlW[r0 + tg];     al[mt][1] = AlW[r1 + tg];
            al[mt][2] = AlW[r0 + tg + 4]; al[mt][3] = AlW[r1 + tg + 4];
        }
#pragma unroll
        for (int nt = 0; nt < 8; nt++) {
            int nr = (nbase + nt * 8 + g) * 12;
            uint32_t bh0 = BhW[nr + tg], bh1 = BhW[nr + tg + 4];
            uint32_t bl0 = BlW[nr + tg], bl1 = BlW[nr + tg + 4];
#pragma unroll
            for (int mt = 0; mt < 2; mt++) {
                mma_bf16(acc[mt][nt], ah[mt], bh0, bh1);
                mma_bf16(acc[mt][nt], ah[mt], bl0, bl1);
                mma_bf16(acc[mt][nt], al[mt], bh0, bh1);
            }
        }
        __syncthreads();

        if (it + 3 < nk) {
            uint32_t st = sb + buf * STG_B;
            int k0 = (it + 3) * BK;
            cpa16(st + dOff,         pAh + k0, asz);
            cpa16(st + 6144 + dOff,  pAl + k0, asz);
            cpa16(st + 12288 + dOff, pBh + k0, bsz);
            cpa16(st + 18432 + dOff, pBl + k0, bsz);
        }
        CP_COMMIT();
        buf = (buf == 2) ? 0 : buf + 1;
    }

    // epilogue
#pragma unroll
    for (int mt = 0; mt < 2; mt++) {
#pragma unroll
        for (int nt = 0; nt < 8; nt++) {
            int gc = n0 + nbase + nt * 8 + tg * 2;
            if (gc >= Nn) continue;
            int gm0 = m0 + mbase + mt * 16 + g;
#pragma unroll
            for (int hrow = 0; hrow < 2; hrow++) {
                int gmr = gm0 + hrow * 8;
                if (gmr >= Mloc) continue;
                int crow = (MODE == 0) ? gmr : (base + gmr);
                size_t off = (size_t)crow * Nn + gc;
                float2 vv = make_float2(acc[mt][nt][hrow * 2], acc[mt][nt][hrow * 2 + 1]);
                if (MODE == 0 && addp) {
                    float2 rv = *(const float2*)(addp + off);
                    vv.x += rv.x; vv.y += rv.y;
                }
                *(float2*)(C + off) = vv;
            }
        }
    }
}

// ---------------- weight split: fp32 -> bf16 hi/lo planes ----------------
__global__ void splitw_k(const float* __restrict__ src, bf16* __restrict__ h,
                         bf16* __restrict__ l, int n4) {
    for (int i = blockIdx.x * 256 + threadIdx.x; i < n4; i += gridDim.x * 256) {
        float4 v = *(const float4*)(src + i * 4);
        uint32_t h0, l0, h1, l1;
        split2(v.x, v.y, h0, l0);
        split2(v.z, v.w, h1, l1);
        *(uint32_t*)(h + i * 4)     = h0;
        *(uint32_t*)(h + i * 4 + 2) = h1;
        *(uint32_t*)(l + i * 4)     = l0;
        *(uint32_t*)(l + i * 4 + 2) = l1;
    }
}

// ---------------- RMSNorm with split output ----------------
__global__ void rmsnorm_sp_k(const float* __restrict__ x, const float* __restrict__ w,
                             float* __restrict__ o, bf16* __restrict__ oh,
                             bf16* __restrict__ ol) {
    int n = blockIdx.x;
    const float* xr = x + (size_t)n * D_;
    float s = 0.f;
    for (int d = threadIdx.x; d < D_; d += 256) { float v = xr[d]; s += v * v; }
    __shared__ float red[256];
    red[threadIdx.x] = s; __syncthreads();
    for (int st = 128; st > 0; st >>= 1) {
        if (threadIdx.x < st) red[threadIdx.x] += red[threadIdx.x + st];
        __syncthreads();
    }
    float inv = rsqrtf(red[0] / (float)D_ + 1e-6f);
    size_t ro = (size_t)n * D_;
    for (int d = threadIdx.x; d < D_; d += 256) {
        float v = xr[d] * inv * w[d];
        if (o) o[ro + d] = v;
        bf16 h, l;
        split1(v, h, l);
        oh[ro + d] = h; ol[ro + d] = l;
    }
}

// ---------------- RoPE (in-place on q,k) ----------------
__global__ void rope_k(float* __restrict__ q, float* __restrict__ k,
                       const int* __restrict__ pos) {
    int idx = blockIdx.x * 256 + threadIdx.x;
    if (idx >= NTOK * HN * 64) return;
    int j  = idx & 63;
    int hh = (idx >> 6) & 15;
    int t  = idx >> 10;
    float p = (float)pos[t];
    float inv = expf(-((float)(2 * j) / 128.0f) * 9.210340371976184f);
    float fr = p * inv;
    float sn, cs;
    sincosf(fr, &sn, &cs);
    size_t base = (size_t)t * D_ + hh * HD + j;
    float x1 = q[base], x2 = q[base + 64];
    q[base]      = x1 * cs - x2 * sn;
    q[base + 64] = x2 * cs + x1 * sn;
    x1 = k[base]; x2 = k[base + 64];
    k[base]      = x1 * cs - x2 * sn;
    k[base + 64] = x2 * cs + x1 * sn;
}

// ---------------- split Q/K into bf16 hi/lo ----------------
__global__ void splitqk_k() {
    int i = blockIdx.x * 256 + threadIdx.x;
    if (i >= NTOK * D_) return;
    bf16 h, l;
    split1(g_q[i], h, l); g_qh[i] = h; g_ql[i] = l;
    split1(g_k[i], h, l); g_kh[i] = h; g_kl[i] = l;
}

// ---------------- split V + transpose to [bh][dim][seq] bf16 hi/lo ----------------
__global__ void splitv_k() {
    __shared__ bf16 sh[32][33], sl[32][33];
    int tx = threadIdx.x, ty = threadIdx.y;      // (32, 8)
    int s0 = blockIdx.x * 32;
    int d0 = blockIdx.y * 32;
    int bh = blockIdx.z;
    int b = bh >> 4, hh = bh & 15;
#pragma unroll
    for (int i = 0; i < 4; i++) {
        int sr = ty + i * 8;
        float v = g_v[((size_t)(b * SQ + s0 + sr)) * D_ + hh * HD + d0 + tx];
        bf16 h, l;
        split1(v, h, l);
        sh[sr][tx] = h; sl[sr][tx] = l;
    }
    __syncthreads();
#pragma unroll
    for (int i = 0; i < 4; i++) {
        int dr = ty + i * 8;
        size_t o = ((size_t)bh * HD + d0 + dr) * SQ + s0 + tx;
        g_vth[o] = sh[tx][dr];
        g_vtl[o] = sl[tx][dr];
    }
}

// ---------------- flash attention via mma.sync bf16x3 ----------------
// grid (SQ/64, HN, BB), block 128. Warp w owns 16 q rows. Epilogue writes hi/lo planes.
__global__ void __launch_bounds__(128) attn_mma_k()
{
    int w = threadIdx.x >> 5, lane = threadIdx.x & 31;
    int g = lane >> 2, tg = lane & 3;
    int hh = blockIdx.y, b = blockIdx.z;
    int qs0 = blockIdx.x * 64 + w * 16;
    int bh = b * HN + hh;

    uint32_t qfh[8][4], qfl[8][4];
    size_t qr0 = ((size_t)(b * SQ + qs0 + g)) * D_ + hh * HD;
    size_t qr1 = qr0 + (size_t)8 * D_;
#pragma unroll
    for (int ks = 0; ks < 8; ks++) {
        int c0 = ks * 16 + 2 * tg;
        qfh[ks][0] = *(const uint32_t*)&g_qh[qr0 + c0];
        qfh[ks][1] = *(const uint32_t*)&g_qh[qr1 + c0];
        qfh[ks][2] = *(const uint32_t*)&g_qh[qr0 + c0 + 8];
        qfh[ks][3] = *(const uint32_t*)&g_qh[qr1 + c0 + 8];
        qfl[ks][0] = *(const uint32_t*)&g_ql[qr0 + c0];
        qfl[ks][1] = *(const uint32_t*)&g_ql[qr1 + c0];
        qfl[ks][2] = *(const uint32_t*)&g_ql[qr0 + c0 + 8];
        qfl[ks][3] = *(const uint32_t*)&g_ql[qr1 + c0 + 8];
    }

    float m0 = -1e30f, m1 = -1e30f, l0 = 0.f, l1 = 0.f;
    float Oa[16][4];
#pragma unroll
    for (int nt = 0; nt < 16; nt++)
#pragma unroll
        for (int q = 0; q < 4; q++) Oa[nt][q] = 0.f;

    const float SC = 0.08838834764831845f;
    int row0 = qs0 + g, row1 = row0 + 8;

    for (int kt = 0; kt <= qs0 + 15; kt += 32) {
        float s[4][4];
#pragma unroll
        for (int nt = 0; nt < 4; nt++)
#pragma unroll
            for (int q = 0; q < 4; q++) s[nt][q] = 0.f;

        size_t kb = ((size_t)(b * SQ + kt)) * D_ + hh * HD;
#pragma unroll
        for (int ks = 0; ks < 8; ks++) {
            int c0 = ks * 16 + 2 * tg;
#pragma unroll
            for (int nt = 0; nt < 4; nt++) {
                size_t kr = kb + (size_t)(nt * 8 + g) * D_;
                uint32_t bh0 = *(const uint32_t*)&g_kh[kr + c0];
                uint32_t bh1 = *(const uint32_t*)&g_kh[kr + c0 + 8];
                uint32_t bl0 = *(const uint32_t*)&g_kl[kr + c0];
                uint32_t bl1 = *(const uint32_t*)&g_kl[kr + c0 + 8];
                mma_bf16(s[nt], qfh[ks], bh0, bh1);
                mma_bf16(s[nt], qfh[ks], bl0, bl1);
                mma_bf16(s[nt], qfl[ks], bh0, bh1);
            }
        }

#pragma unroll
        for (int nt = 0; nt < 4; nt++) {
            int col = kt + nt * 8 + 2 * tg;
            s[nt][0] = (col     <= row0) ? s[nt][0] * SC : -1e30f;
            s[nt][1] = (col + 1 <= row0) ? s[nt][1] * SC : -1e30f;
            s[nt][2] = (col     <= row1) ? s[nt][2] * SC : -1e30f;
            s[nt][3] = (col + 1 <= row1) ? s[nt][3] * SC : -1e30f;
        }

        float mx0 = -1e30f, mx1 = -1e30f;
#pragma unroll
        for (int nt = 0; nt < 4; nt++) {
            mx0 = fmaxf(mx0, fmaxf(s[nt][0], s[nt][1]));
            mx1 = fmaxf(mx1, fmaxf(s[nt][2], s[nt][3]));
        }
        mx0 = fmaxf(mx0, __shfl_xor_sync(0xffffffff, mx0, 1));
        mx0 = fmaxf(mx0, __shfl_xor_sync(0xffffffff, mx0, 2));
        mx1 = fmaxf(mx1, __shfl_xor_sync(0xffffffff, mx1, 1));
        mx1 = fmaxf(mx1, __shfl_xor_sync(0xffffffff, mx1, 2));
        float mn0 = fmaxf(m0, mx0), mn1 = fmaxf(m1, mx1);
        float a0 = __expf(m0 - mn0), a1 = __expf(m1 - mn1);
        float sum0 = 0.f, sum1 = 0.f;
#pragma unroll
        for (int nt = 0; nt < 4; nt++) {
            s[nt][0] = __expf(s[nt][0] - mn0);
            s[nt][1] = __expf(s[nt][1] - mn0);
            s[nt][2] = __expf(s[nt][2] - mn1);
            s[nt][3] = __expf(s[nt][3] - mn1);
            sum0 += s[nt][0] + s[nt][1];
            sum1 += s[nt][2] + s[nt][3];
        }
        sum0 += __shfl_xor_sync(0xffffffff, sum0, 1);
        sum0 += __shfl_xor_sync(0xffffffff, sum0, 2);
        sum1 += __shfl_xor_sync(0xffffffff, sum1, 1);
        sum1 += __shfl_xor_sync(0xffffffff, sum1, 2);
        l0 = l0 * a0 + sum0; l1 = l1 * a1 + sum1;
        m0 = mn0; m1 = mn1;

#pragma unroll
        for (int nt = 0; nt < 16; nt++) {
            Oa[nt][0] *= a0; Oa[nt][1] *= a0;
            Oa[nt][2] *= a1; Oa[nt][3] *= a1;
        }

        uint32_t pah[2][4], pal[2][4];
#pragma unroll
        for (int ks2 = 0; ks2 < 2; ks2++) {
            int na = ks2 * 2, nb = na + 1;
            split2(s[na][0], s[na][1], pah[ks2][0], pal[ks2][0]);
            split2(s[na][2], s[na][3], pah[ks2][1], pal[ks2][1]);
            split2(s[nb][0], s[nb][1], pah[ks2][2], pal[ks2][2]);
            split2(s[nb][2], s[nb][3], pah[ks2][3], pal[ks2][3]);
        }

#pragma unroll
        for (int ks2 = 0; ks2 < 2; ks2++) {
            int st = kt + ks2 * 16 + 2 * tg;
#pragma unroll
            for (int nt = 0; nt < 16; nt++) {
                size_t vr = ((size_t)bh * HD + nt * 8 + g) * SQ + st;
                uint32_t vh0 = *(const uint32_t*)&g_vth[vr];
                uint32_t vh1 = *(const uint32_t*)&g_vth[vr + 8];
                uint32_t vl0 = *(const uint32_t*)&g_vtl[vr];
                uint32_t vl1 = *(const uint32_t*)&g_vtl[vr + 8];
                mma_bf16(Oa[nt], pah[ks2], vh0, vh1);
                mma_bf16(Oa[nt], pah[ks2], vl0, vl1);
                mma_bf16(Oa[nt], pal[ks2], vh0, vh1);
            }
        }
    }

    // epilogue: split O into hi/lo planes for the O-projection GEMM
    float i0 = 1.f / l0, i1 = 1.f / l1;
    size_t or0 = ((size_t)(b * SQ + qs0 + g)) * D_ + hh * HD;
    size_t or1 = or0 + (size_t)8 * D_;
#pragma unroll
    for (int nt = 0; nt < 16; nt++) {
        int col = nt * 8 + 2 * tg;
        uint32_t h, l;
        split2(Oa[nt][0] * i0, Oa[nt][1] * i0, h, l);
        *(uint32_t*)&g_ah[or0 + col] = h;
        *(uint32_t*)&g_al[or0 + col] = l;
        split2(Oa[nt][2] * i1, Oa[nt][3] * i1, h, l);
        *(uint32_t*)&g_ah[or1 + col] = h;
        *(uint32_t*)&g_al[or1 + col] = l;
    }
}

// ---------------- MoE routing ----------------
__global__ void zero_k() {
    if (threadIdx.x < EE) { g_cnt[threadIdx.x] = 0; g_cur[threadIdx.x] = 0; }
}

__global__ void route1_k(const float* __restrict__ x, const float* __restrict__ gw) {
    int n = blockIdx.x;
    float part[EE];
#pragma unroll
    for (int e = 0; e < EE; e++) part[e] = 0.f;
    for (int d = threadIdx.x; d < D_; d += 256) {
        float xv = x[(size_t)n * D_ + d];
#pragma unroll
        for (int e = 0; e < EE; e++) part[e] = fmaf(xv, gw[e * D_ + d], part[e]);
    }
    __shared__ float red[256];
    __shared__ float lg[EE];
    for (int e = 0; e < EE; e++) {
        red[threadIdx.x] = part[e]; __syncthreads();
        for (int st = 128; st > 0; st >>= 1) {
            if (threadIdx.x < st) red[threadIdx.x] += red[threadIdx.x + st];
            __syncthreads();
        }
        if (threadIdx.x == 0) lg[e] = red[0];
        __syncthreads();
    }
    if (threadIdx.x == 0) {
        int i0 = 0; float b0 = lg[0];
        for (int e = 1; e < EE; e++) if (lg[e] > b0) { b0 = lg[e]; i0 = e; }
        int i1 = -1; float b1 = -1e30f;
        for (int e = 0; e < EE; e++) { if (e == i0) continue; if (lg[e] > b1) { b1 = lg[e]; i1 = e; } }
        float m = fmaxf(b0, b1);
        float w0 = __expf(b0 - m), w1 = __expf(b1 - m);
        float s = w0 + w1; w0 /= s; w1 /= s;
        g_tope[n*2] = i0; g_tope[n*2+1] = i1;
        g_topw[n*2] = w0; g_topw[n*2+1] = w1;
        atomicAdd(&g_cnt[i0], 1); atomicAdd(&g_cnt[i1], 1);
    }
}

__global__ void scan_k() {
    int o = 0;
    for (int e = 0; e < EE; e++) { g_off[e] = o; o += g_cnt[e]; }
}

__global__ void assign_k() {
    int n = blockIdx.x * 256 + threadIdx.x;
    if (n >= NTOK) return;
#pragma unroll
    for (int kk = 0; kk < 2; kk++) {
        int e = g_tope[n*2 + kk];
        int p = g_off[e] + atomicAdd(&g_cur[e], 1);
        g_slot_tok[p] = n;
        g_slot_w[p]   = g_topw[n*2 + kk];
        g_tok_pos[n*2 + kk] = p;
    }
}

// ---------------- swiglu with split output ----------------
__global__ void swiglu_k() {
    int i = blockIdx.x * 256 + threadIdx.x;
    if (i >= NSLOT * DE_) return;
    float g = g_gb[i], u = g_ub[i];
    float sig = 1.f / (1.f + __expf(-g));
    float v = g * sig * u;
    bf16 h, l;
    split1(v, h, l);
    g_ih[i] = h; g_il[i] = l;
}

__global__ void final_k(float* __restrict__ out) {
    int n = blockIdx.x;
    int p0 = g_tok_pos[n*2], p1 = g_tok_pos[n*2 + 1];
    float w0 = g_slot_w[p0], w1 = g_slot_w[p1];
    size_t hb = (size_t)n * D_;
    for (int d = threadIdx.x * 4; d < D_; d += 1024) {
        float4 hv = *(const float4*)(g_h + hb + d);
        float4 a  = *(const float4*)(g_op + (size_t)p0 * D_ + d);
        float4 b4 = *(const float4*)(g_op + (size_t)p1 * D_ + d);
        float4 o;
        o.x = hv.x + w0 * a.x + w1 * b4.x;
        o.y = hv.y + w0 * a.y + w1 * b4.y;
        o.z = hv.z + w0 * a.z + w1 * b4.z;
        o.w = hv.w + w0 * a.w + w1 * b4.w;
        *(float4*)(out + hb + d) = o;
    }
}

// ---------------- launcher ----------------
extern "C" void kernel_launch(void* const* d_in, const int* in_sizes, int n_in,
                              void* d_out, int out_size) {
    const float* hidden = (const float*)d_in[0];
    const float* ln1    = (const float*)d_in[1];
    const float* ln2    = (const float*)d_in[2];
    const float* qw     = (const float*)d_in[3];
    const float* kw     = (const float*)d_in[4];
    const float* vw     = (const float*)d_in[5];
    const float* ow     = (const float*)d_in[6];
    const float* gw     = (const float*)d_in[7];
    const float* egw    = (const float*)d_in[8];
    const float* euw    = (const float*)d_in[9];
    const float* edw    = (const float*)d_in[10];
    const int*   pos    = (const int*)d_in[11];
    float* out = (float*)d_out;

    float *qb, *kb, *vb, *hb, *x2, *gb, *ub, *op;
    cudaGetSymbolAddress((void**)&qb, g_q);
    cudaGetSymbolAddress((void**)&kb, g_k);
    cudaGetSymbolAddress((void**)&vb, g_v);
    cudaGetSymbolAddress((void**)&hb, g_h);
    cudaGetSymbolAddress((void**)&x2, g_xn2);
    cudaGetSymbolAddress((void**)&gb, g_gb);
    cudaGetSymbolAddress((void**)&ub, g_ub);
    cudaGetSymbolAddress((void**)&op, g_op);

    bf16 *xnh, *xnl, *ah, *al, *x2h, *x2l, *ih, *il;
    bf16 *wqh, *wql, *wkh, *wkl, *wvh, *wvl, *woh, *wol;
    bf16 *egh, *egl, *euh, *eul, *edh, *edl;
    cudaGetSymbolAddress((void**)&xnh, g_xnh); cudaGetSymbolAddress((void**)&xnl, g_xnl);
    cudaGetSymbolAddress((void**)&ah,  g_ah);  cudaGetSymbolAddress((void**)&al,  g_al);
    cudaGetSymbolAddress((void**)&x2h, g_x2h); cudaGetSymbolAddress((void**)&x2l, g_x2l);
    cudaGetSymbolAddress((void**)&ih,  g_ih);  cudaGetSymbolAddress((void**)&il,  g_il);
    cudaGetSymbolAddress((void**)&wqh, g_wqh); cudaGetSymbolAddress((void**)&wql, g_wql);
    cudaGetSymbolAddress((void**)&wkh, g_wkh); cudaGetSymbolAddress((void**)&wkl, g_wkl);
    cudaGetSymbolAddress((void**)&wvh, g_wvh); cudaGetSymbolAddress((void**)&wvl, g_wvl);
    cudaGetSymbolAddress((void**)&woh, g_woh); cudaGetSymbolAddress((void**)&wol, g_wol);
    cudaGetSymbolAddress((void**)&egh, g_egh); cudaGetSymbolAddress((void**)&egl, g_egl);
    cudaGetSymbolAddress((void**)&euh, g_euh); cudaGetSymbolAddress((void**)&eul, g_eul);
    cudaGetSymbolAddress((void**)&edh, g_edh); cudaGetSymbolAddress((void**)&edl, g_edl);

    cudaFuncSetAttribute(gemm_bf3<0>, cudaFuncAttributeMaxDynamicSharedMemorySize, GSMEM);
    cudaFuncSetAttribute(gemm_bf3<1>, cudaFuncAttributeMaxDynamicSharedMemorySize, GSMEM);
    cudaFuncSetAttribute(gemm_bf3<2>, cudaFuncAttributeMaxDynamicSharedMemorySize, GSMEM);

    // 0. pre-split all weights into bf16 hi/lo planes
    splitw_k<<<512, 256>>>(qw,  wqh, wql, D_*D_/4);
    splitw_k<<<512, 256>>>(kw,  wkh, wkl, D_*D_/4);
    splitw_k<<<512, 256>>>(vw,  wvh, wvl, D_*D_/4);
    splitw_k<<<512, 256>>>(ow,  woh, wol, D_*D_/4);
    splitw_k<<<1024, 256>>>(egw, egh, egl, EE*DE_*D_/4);
    splitw_k<<<1024, 256>>>(euw, euh, eul, EE*DE_*D_/4);
    splitw_k<<<1024, 256>>>(edw, edh, edl, EE*D_*DE_/4);

    // 1. pre-attention RMSNorm (split output)
    rmsnorm_sp_k<<<NTOK, 256>>>(hidden, ln1, nullptr, xnh, xnl);

    // 2. QKV projections
    dim3 gdense(D_ / TN, NTOK / TM, 1);
    gemm_bf3<0><<<gdense, 256, GSMEM>>>(xnh, xnl, wqh, wql, qb, nullptr, NTOK, D_, D_, 0);
    gemm_bf3<0><<<gdense, 256, GSMEM>>>(xnh, xnl, wkh, wkl, kb, nullptr, NTOK, D_, D_, 0);
    gemm_bf3<0><<<gdense, 256, GSMEM>>>(xnh, xnl, wvh, wvl, vb, nullptr, NTOK, D_, D_, 0);

    // 3. RoPE
    rope_k<<<(NTOK * HN * 64) / 256, 256>>>(qb, kb, pos);

    // 4. split + attention
    splitqk_k<<<(NTOK * D_) / 256, 256>>>();
    splitv_k<<<dim3(SQ / 32, HD / 32, BB * HN), dim3(32, 8)>>>();
    attn_mma_k<<<dim3(SQ / 64, HN, BB), 128>>>();

    // 5. O projection + residual
    gemm_bf3<0><<<gdense, 256, GSMEM>>>(ah, al, woh, wol, hb, hidden, NTOK, D_, D_, 0);

    // 6. post-attention RMSNorm (fp32 for routing + split for GEMMs)
    rmsnorm_sp_k<<<NTOK, 256>>>(hb, ln2, x2, x2h, x2l);

    // 7. routing
    zero_k<<<1, 32>>>();
    route1_k<<<NTOK, 256>>>(x2, gw);
    scan_k<<<1, 1>>>();
    assign_k<<<NTOK / 256, 256>>>();

    // 8. MoE expert GEMMs
    gemm_bf3<1><<<dim3((DE_ + TN - 1) / TN, 16, EE), 256, GSMEM>>>(
        x2h, x2l, egh, egl, gb, nullptr, 0, DE_, D_, (long)DE_ * D_);
    gemm_bf3<1><<<dim3((DE_ + TN - 1) / TN, 16, EE), 256, GSMEM>>>(
        x2h, x2l, euh, eul, ub, nullptr, 0, DE_, D_, (long)DE_ * D_);
    swiglu_k<<<(NSLOT * DE_ + 255) / 256, 256>>>();
    gemm_bf3<2><<<dim3(D_ / TN, 16, EE), 256, GSMEM>>>(
        ih, il, edh, edl, op, nullptr, 0, D_, DE_, (long)D_ * DE_);

    // 9. weighted combine + residual
    final_k<<<NTOK, 256>>>(out);
}

// round 11
// speedup vs baseline: 1.3494x; 1.3494x over previous
#include <cuda_runtime.h>
#include <cuda_bf16.h>
#include <math.h>
#include <stdint.h>

// ---------------- problem constants ----------------
#define BB 2
#define SQ 1024
#define D_ 2048
#define HN 16
#define HD 128
#define NTOK (BB*SQ)       // 2048
#define EE 8
#define DE_ 704
#define NSLOT (NTOK*2)     // 4096 (top-2 per token)

typedef __nv_bfloat16 bf16;

// ---------------- scratch (device globals: no allocations allowed) ----------------
__device__ float g_q   [NTOK*D_];
__device__ float g_k   [NTOK*D_];
__device__ float g_v   [NTOK*D_];
__device__ float g_attn[NTOK*D_];
__device__ float g_h   [NTOK*D_];
__device__ float g_xn  [NTOK*D_];
__device__ float g_xn2 [NTOK*D_];
__device__ float g_gb  [NSLOT*DE_];
__device__ float g_ub  [NSLOT*DE_];
__device__ float g_op  [NSLOT*D_];
__device__ int   g_cnt [EE];
__device__ int   g_cur [EE];
__device__ int   g_off [EE];
__device__ int   g_tope[NTOK*2];
__device__ float g_topw[NTOK*2];
__device__ int   g_slot_tok[NSLOT];
__device__ float g_slot_w  [NSLOT];
__device__ int   g_tok_pos [NTOK*2];
// bf16 hi/lo planes for attention
__device__ bf16 g_qh[NTOK*D_], g_ql[NTOK*D_];
__device__ bf16 g_kh[NTOK*D_], g_kl[NTOK*D_];
__device__ bf16 g_vth[NTOK*D_], g_vtl[NTOK*D_];   // V transposed [bh][HD][SQ]

// ---------------- helpers ----------------
__device__ __forceinline__ uint32_t smem_u32(const void* p) {
    uint32_t a;
    asm("{ .reg .u64 t; cvta.to.shared.u64 t, %1; cvt.u32.u64 %0, t; }" : "=r"(a) : "l"(p));
    return a;
}
__device__ __forceinline__ void mma_bf16(float* c, const uint32_t* a,
                                         uint32_t b0, uint32_t b1) {
    asm volatile(
        "mma.sync.aligned.m16n8k16.row.col.f32.bf16.bf16.f32 "
        "{%0,%1,%2,%3}, {%4,%5,%6,%7}, {%8,%9}, {%0,%1,%2,%3};"
        : "+f"(c[0]), "+f"(c[1]), "+f"(c[2]), "+f"(c[3])
        : "r"(a[0]), "r"(a[1]), "r"(a[2]), "r"(a[3]), "r"(b0), "r"(b1));
}
__device__ __forceinline__ void ldsm4(uint32_t& r0, uint32_t& r1, uint32_t& r2,
                                      uint32_t& r3, uint32_t addr) {
    asm volatile("ldmatrix.sync.aligned.m8n8.x4.shared.b16 {%0,%1,%2,%3}, [%4];"
                 : "=r"(r0), "=r"(r1), "=r"(r2), "=r"(r3) : "r"(addr));
}
__device__ __forceinline__ void split2(float x0, float x1, uint32_t& wh, uint32_t& wl) {
    bf16 h0 = __float2bfloat16(x0);
    bf16 h1 = __float2bfloat16(x1);
    bf16 l0 = __float2bfloat16(x0 - __bfloat162float(h0));
    bf16 l1 = __float2bfloat16(x1 - __bfloat162float(h1));
    wh = ((uint32_t)__bfloat16_as_ushort(h1) << 16) | __bfloat16_as_ushort(h0);
    wl = ((uint32_t)__bfloat16_as_ushort(l1) << 16) | __bfloat16_as_ushort(l0);
}
__device__ __forceinline__ void split1(float x, bf16& h, bf16& l) {
    h = __float2bfloat16(x);
    l = __float2bfloat16(x - __bfloat162float(h));
}

// ---------------- tensor-core (mma.sync bf16x3, ldmatrix) GEMM ----------------
// C[M,N] = A[M,K] * W[N,K]^T (+add), fp32 in, split in kernel.
// MODE 0: dense. MODE 1: A rows gathered via g_slot_tok. MODE 2: A rows contiguous slots.
#define TM 128
#define TN 128
#define BK 16
#define RS 12   // row stride in 32-bit words (48B) -> conflict-free for LDS & ldmatrix

template<int MODE>
__global__ void __launch_bounds__(256) gemm_mma(
    const float* __restrict__ A, const float* __restrict__ W,
    float* __restrict__ C, const float* __restrict__ addp,
    int M, int Nn, int Kk, long wstride)
{
    __shared__ uint32_t Ah[2][TM][RS];
    __shared__ uint32_t Al[2][TM][RS];
    __shared__ uint32_t Bh[2][TN][RS];
    __shared__ uint32_t Bl[2][TN][RS];

    int e = blockIdx.z;
    int Mloc = M, base = 0;
    const float* Wp = W;
    if (MODE != 0) { Mloc = g_cnt[e]; base = g_off[e]; Wp = W + (size_t)e * (size_t)wstride; }
    int m0 = blockIdx.y * TM;
    if (m0 >= Mloc) return;
    int n0 = blockIdx.x * TN;
    int tid = threadIdx.x;

    const float* aP[2]; const float* bP[2];
    int rowL[2], c4L[2];
    bool aV[2], bV[2];
#pragma unroll
    for (int i = 0; i < 2; i++) {
        int v = tid + i * 256;
        int row = v >> 2, c4 = v & 3;
        rowL[i] = row; c4L[i] = c4;
        int gm = m0 + row;
        bool av = gm < Mloc;
        int arow;
        if (MODE == 0)      arow = av ? gm : 0;
        else if (MODE == 1) arow = av ? g_slot_tok[base + gm] : 0;
        else                arow = av ? (base + gm) : 0;
        aV[i] = av;
        aP[i] = A + (size_t)arow * Kk + c4 * 4;
        int gn = n0 + row;
        bV[i] = gn < Nn;
        bP[i] = Wp + (size_t)(bV[i] ? gn : 0) * Kk + c4 * 4;
    }

    int lane = tid & 31, g = lane >> 2, tg = lane & 3;
    int wm = (tid >> 5) & 3;
    int wn = tid >> 7;
    int mbase = wm * 32, nbase = wn * 64;

    // ldmatrix per-thread address offsets (bytes within one buffer plane)
    uint32_t sAh = smem_u32(Ah), sAl = smem_u32(Al);
    uint32_t sBh = smem_u32(Bh), sBl = smem_u32(Bl);
    uint32_t aoff[2], boff[4];
#pragma unroll
    for (int mt = 0; mt < 2; mt++)
        aoff[mt] = (uint32_t)((mbase + mt * 16 + (lane & 7) + ((lane >> 3) & 1) * 8) * 48
                              + ((lane >> 4) & 1) * 16);
#pragma unroll
    for (int p = 0; p < 4; p++)
        boff[p] = (uint32_t)((nbase + p * 16 + (lane & 7) + ((lane >> 4) & 1) * 8) * 48
                             + ((lane >> 3) & 1) * 16);

    float acc[2][8][4];
#pragma unroll
    for (int mt = 0; mt < 2; mt++)
#pragma unroll
        for (int nt = 0; nt < 8; nt++)
#pragma unroll
            for (int q = 0; q < 4; q++) acc[mt][nt][q] = 0.f;

    int nk = Kk / BK;
    float4 ra[2], rb[2];
#pragma unroll
    for (int i = 0; i < 2; i++) {
        ra[i] = aV[i] ? *(const float4*)(aP[i]) : make_float4(0,0,0,0);
        rb[i] = bV[i] ? *(const float4*)(bP[i]) : make_float4(0,0,0,0);
    }

    int buf = 0;
    for (int it = 0; it < nk; it++) {
        // split+store current regs to smem
#pragma unroll
        for (int i = 0; i < 2; i++) {
            int r = rowL[i], w0 = c4L[i] * 2;
            uint32_t h0, l0, h1, l1;
            split2(ra[i].x, ra[i].y, h0, l0);
            split2(ra[i].z, ra[i].w, h1, l1);
            Ah[buf][r][w0] = h0; Ah[buf][r][w0+1] = h1;
            Al[buf][r][w0] = l0; Al[buf][r][w0+1] = l1;
            split2(rb[i].x, rb[i].y, h0, l0);
            split2(rb[i].z, rb[i].w, h1, l1);
            Bh[buf][r][w0] = h0; Bh[buf][r][w0+1] = h1;
            Bl[buf][r][w0] = l0; Bl[buf][r][w0+1] = l1;
        }
        if (it + 1 < nk) {
            int k0 = (it + 1) * BK;
#pragma unroll
            for (int i = 0; i < 2; i++) {
                ra[i] = aV[i] ? *(const float4*)(aP[i] + k0) : make_float4(0,0,0,0);
                rb[i] = bV[i] ? *(const float4*)(bP[i] + k0) : make_float4(0,0,0,0);
            }
        }
        __syncthreads();

        uint32_t bufo = (uint32_t)buf * (TM * RS * 4);
        uint32_t ah[2][4], al[2][4];
#pragma unroll
        for (int mt = 0; mt < 2; mt++) {
            ldsm4(ah[mt][0], ah[mt][1], ah[mt][2], ah[mt][3], sAh + bufo + aoff[mt]);
            ldsm4(al[mt][0], al[mt][1], al[mt][2], al[mt][3], sAl + bufo + aoff[mt]);
        }
#pragma unroll
        for (int p = 0; p < 4; p++) {
            uint32_t b00, b01, b10, b11, c00, c01, c10, c11;
            ldsm4(b00, b01, b10, b11, sBh + bufo + boff[p]);
            ldsm4(c00, c01, c10, c11, sBl + bufo + boff[p]);
#pragma unroll
            for (int mt = 0; mt < 2; mt++) {
                mma_bf16(acc[mt][2*p],   ah[mt], b00, b01);
                mma_bf16(acc[mt][2*p],   ah[mt], c00, c01);
                mma_bf16(acc[mt][2*p],   al[mt], b00, b01);
                mma_bf16(acc[mt][2*p+1], ah[mt], b10, b11);
                mma_bf16(acc[mt][2*p+1], ah[mt], c10, c11);
                mma_bf16(acc[mt][2*p+1], al[mt], b10, b11);
            }
        }
        buf ^= 1;
        // single barrier per stage is safe with 2 buffers (writes target the
        // buffer last read two iterations ago, fenced by the intervening sync)
    }

    // epilogue: c0/c1 -> (row g, cols 2tg,2tg+1), c2/c3 -> row g+8
#pragma unroll
    for (int mt = 0; mt < 2; mt++) {
#pragma unroll
        for (int nt = 0; nt < 8; nt++) {
            int gc = n0 + nbase + nt * 8 + tg * 2;
            if (gc >= Nn) continue;
            int gm0 = m0 + mbase + mt * 16 + g;
#pragma unroll
            for (int hrow = 0; hrow < 2; hrow++) {
                int gm = gm0 + hrow * 8;
                if (gm >= Mloc) continue;
                int crow = (MODE == 0) ? gm : (base + gm);
                size_t off = (size_t)crow * Nn + gc;
                float2 vv = make_float2(acc[mt][nt][hrow * 2], acc[mt][nt][hrow * 2 + 1]);
                if (MODE == 0 && addp) {
                    float2 rv = *(const float2*)(addp + off);
                    vv.x += rv.x; vv.y += rv.y;
                }
                *(float2*)(C + off) = vv;
            }
        }
    }
}

// ---------------- RMSNorm ----------------
__global__ void rmsnorm_k(const float* __restrict__ x, const float* __restrict__ w,
                          float* __restrict__ o) {
    int n = blockIdx.x;
    const float* xr = x + (size_t)n * D_;
    float s = 0.f;
    for (int d = threadIdx.x; d < D_; d += 256) { float v = xr[d]; s += v * v; }
    __shared__ float red[256];
    red[threadIdx.x] = s; __syncthreads();
    for (int st = 128; st > 0; st >>= 1) {
        if (threadIdx.x < st) red[threadIdx.x] += red[threadIdx.x + st];
        __syncthreads();
    }
    float inv = rsqrtf(red[0] / (float)D_ + 1e-6f);
    float* orow = o + (size_t)n * D_;
    for (int d = threadIdx.x; d < D_; d += 256) orow[d] = xr[d] * inv * w[d];
}

// ---------------- fused RoPE + bf16 hi/lo split for Q,K ----------------
__global__ void rope_split_k(const int* __restrict__ pos) {
    int idx = blockIdx.x * 256 + threadIdx.x;
    if (idx >= NTOK * HN * 64) return;
    int j  = idx & 63;
    int hh = (idx >> 6) & 15;
    int t  = idx >> 10;
    float p = (float)pos[t];
    float inv = expf(-((float)(2 * j) / 128.0f) * 9.210340371976184f);
    float fr = p * inv;
    float sn, cs;
    sincosf(fr, &sn, &cs);
    size_t base = (size_t)t * D_ + hh * HD + j;
    bf16 h, l;
    float x1 = g_q[base], x2 = g_q[base + 64];
    float r1 = x1 * cs - x2 * sn, r2 = x2 * cs + x1 * sn;
    split1(r1, h, l); g_qh[base] = h;      g_ql[base] = l;
    split1(r2, h, l); g_qh[base + 64] = h; g_ql[base + 64] = l;
    x1 = g_k[base]; x2 = g_k[base + 64];
    r1 = x1 * cs - x2 * sn; r2 = x2 * cs + x1 * sn;
    split1(r1, h, l); g_kh[base] = h;      g_kl[base] = l;
    split1(r2, h, l); g_kh[base + 64] = h; g_kl[base + 64] = l;
}

// ---------------- split V + transpose to [bh][dim][seq] bf16 hi/lo ----------------
__global__ void splitv_k() {
    __shared__ bf16 sh[32][33], sl[32][33];
    int tx = threadIdx.x, ty = threadIdx.y;      // (32, 8)
    int s0 = blockIdx.x * 32;
    int d0 = blockIdx.y * 32;
    int bh = blockIdx.z;
    int b = bh >> 4, hh = bh & 15;
#pragma unroll
    for (int i = 0; i < 4; i++) {
        int sr = ty + i * 8;
        float v = g_v[((size_t)(b * SQ + s0 + sr)) * D_ + hh * HD + d0 + tx];
        bf16 h, l;
        split1(v, h, l);
        sh[sr][tx] = h; sl[sr][tx] = l;
    }
    __syncthreads();
#pragma unroll
    for (int i = 0; i < 4; i++) {
        int dr = ty + i * 8;
        size_t o = ((size_t)bh * HD + d0 + dr) * SQ + s0 + tx;
        g_vth[o] = sh[tx][dr];
        g_vtl[o] = sl[tx][dr];
    }
}

// ---------------- flash attention via mma.sync bf16x3 (no smem, no sync) --------
__global__ void __launch_bounds__(128) attn_mma_k(float* __restrict__ O)
{
    int w = threadIdx.x >> 5, lane = threadIdx.x & 31;
    int g = lane >> 2, tg = lane & 3;
    int hh = blockIdx.y, b = blockIdx.z;
    int qs0 = blockIdx.x * 64 + w * 16;
    int bh = b * HN + hh;

    uint32_t qfh[8][4], qfl[8][4];
    size_t qr0 = ((size_t)(b * SQ + qs0 + g)) * D_ + hh * HD;
    size_t qr1 = qr0 + (size_t)8 * D_;
#pragma unroll
    for (int ks = 0; ks < 8; ks++) {
        int c0 = ks * 16 + 2 * tg;
        qfh[ks][0] = *(const uint32_t*)&g_qh[qr0 + c0];
        qfh[ks][1] = *(const uint32_t*)&g_qh[qr1 + c0];
        qfh[ks][2] = *(const uint32_t*)&g_qh[qr0 + c0 + 8];
        qfh[ks][3] = *(const uint32_t*)&g_qh[qr1 + c0 + 8];
        qfl[ks][0] = *(const uint32_t*)&g_ql[qr0 + c0];
        qfl[ks][1] = *(const uint32_t*)&g_ql[qr1 + c0];
        qfl[ks][2] = *(const uint32_t*)&g_ql[qr0 + c0 + 8];
        qfl[ks][3] = *(const uint32_t*)&g_ql[qr1 + c0 + 8];
    }

    float m0 = -1e30f, m1 = -1e30f, l0 = 0.f, l1 = 0.f;
    float Oa[16][4];
#pragma unroll
    for (int nt = 0; nt < 16; nt++)
#pragma unroll
        for (int q = 0; q < 4; q++) Oa[nt][q] = 0.f;

    const float SC = 0.08838834764831845f;
    int row0 = qs0 + g, row1 = row0 + 8;

    for (int kt = 0; kt <= qs0 + 15; kt += 32) {
        float s[4][4];
#pragma unroll
        for (int nt = 0; nt < 4; nt++)
#pragma unroll
            for (int q = 0; q < 4; q++) s[nt][q] = 0.f;

        size_t kb = ((size_t)(b * SQ + kt)) * D_ + hh * HD;
#pragma unroll
        for (int ks = 0; ks < 8; ks++) {
            int c0 = ks * 16 + 2 * tg;
#pragma unroll
            for (int nt = 0; nt < 4; nt++) {
                size_t kr = kb + (size_t)(nt * 8 + g) * D_;
                uint32_t bh0 = *(const uint32_t*)&g_kh[kr + c0];
                uint32_t bh1 = *(const uint32_t*)&g_kh[kr + c0 + 8];
                uint32_t bl0 = *(const uint32_t*)&g_kl[kr + c0];
                uint32_t bl1 = *(const uint32_t*)&g_kl[kr + c0 + 8];
                mma_bf16(s[nt], qfh[ks], bh0, bh1);
                mma_bf16(s[nt], qfh[ks], bl0, bl1);
                mma_bf16(s[nt], qfl[ks], bh0, bh1);
            }
        }

#pragma unroll
        for (int nt = 0; nt < 4; nt++) {
            int col = kt + nt * 8 + 2 * tg;
            s[nt][0] = (col     <= row0) ? s[nt][0] * SC : -1e30f;
            s[nt][1] = (col + 1 <= row0) ? s[nt][1] * SC : -1e30f;
            s[nt][2] = (col     <= row1) ? s[nt][2] * SC : -1e30f;
            s[nt][3] = (col + 1 <= row1) ? s[nt][3] * SC : -1e30f;
        }

        float mx0 = -1e30f, mx1 = -1e30f;
#pragma unroll
        for (int nt = 0; nt < 4; nt++) {
            mx0 = fmaxf(mx0, fmaxf(s[nt][0], s[nt][1]));
            mx1 = fmaxf(mx1, fmaxf(s[nt][2], s[nt][3]));
        }
        mx0 = fmaxf(mx0, __shfl_xor_sync(0xffffffff, mx0, 1));
        mx0 = fmaxf(mx0, __shfl_xor_sync(0xffffffff, mx0, 2));
        mx1 = fmaxf(mx1, __shfl_xor_sync(0xffffffff, mx1, 1));
        mx1 = fmaxf(mx1, __shfl_xor_sync(0xffffffff, mx1, 2));
        float mn0 = fmaxf(m0, mx0), mn1 = fmaxf(m1, mx1);
        float a0 = __expf(m0 - mn0), a1 = __expf(m1 - mn1);
        float sum0 = 0.f, sum1 = 0.f;
#pragma unroll
        for (int nt = 0; nt < 4; nt++) {
            s[nt][0] = __expf(s[nt][0] - mn0);
            s[nt][1] = __expf(s[nt][1] - mn0);
            s[nt][2] = __expf(s[nt][2] - mn1);
            s[nt][3] = __expf(s[nt][3] - mn1);
            sum0 += s[nt][0] + s[nt][1];
            sum1 += s[nt][2] + s[nt][3];
        }
        sum0 += __shfl_xor_sync(0xffffffff, sum0, 1);
        sum0 += __shfl_xor_sync(0xffffffff, sum0, 2);
        sum1 += __shfl_xor_sync(0xffffffff, sum1, 1);
        sum1 += __shfl_xor_sync(0xffffffff, sum1, 2);
        l0 = l0 * a0 + sum0; l1 = l1 * a1 + sum1;
        m0 = mn0; m1 = mn1;

#pragma unroll
        for (int nt = 0; nt < 16; nt++) {
            Oa[nt][0] *= a0; Oa[nt][1] *= a0;
            Oa[nt][2] *= a1; Oa[nt][3] *= a1;
        }

        uint32_t pah[2][4], pal[2][4];
#pragma unroll
        for (int ks2 = 0; ks2 < 2; ks2++) {
            int na = ks2 * 2, nb = na + 1;
            split2(s[na][0], s[na][1], pah[ks2][0], pal[ks2][0]);
            split2(s[na][2], s[na][3], pah[ks2][1], pal[ks2][1]);
            split2(s[nb][0], s[nb][1], pah[ks2][2], pal[ks2][2]);
            split2(s[nb][2], s[nb][3], pah[ks2][3], pal[ks2][3]);
        }

#pragma unroll
        for (int ks2 = 0; ks2 < 2; ks2++) {
            int st = kt + ks2 * 16 + 2 * tg;
#pragma unroll
            for (int nt = 0; nt < 16; nt++) {
                size_t vr = ((size_t)bh * HD + nt * 8 + g) * SQ + st;
                uint32_t vh0 = *(const uint32_t*)&g_vth[vr];
                uint32_t vh1 = *(const uint32_t*)&g_vth[vr + 8];
                uint32_t vl0 = *(const uint32_t*)&g_vtl[vr];
                uint32_t vl1 = *(const uint32_t*)&g_vtl[vr + 8];
                mma_bf16(Oa[nt], pah[ks2], vh0, vh1);
                mma_bf16(Oa[nt], pah[ks2], vl0, vl1);
                mma_bf16(Oa[nt], pal[ks2], vh0, vh1);
            }
        }
    }

    float i0 = 1.f / l0, i1 = 1.f / l1;
    size_t or0 = ((size_t)(b * SQ + qs0 + g)) * D_ + hh * HD;
    size_t or1 = or0 + (size_t)8 * D_;
#pragma unroll
    for (int nt = 0; nt < 16; nt++) {
        int col = nt * 8 + 2 * tg;
        *(float2*)&O[or0 + col] = make_float2(Oa[nt][0] * i0, Oa[nt][1] * i0);
        *(float2*)&O[or1 + col] = make_float2(Oa[nt][2] * i1, Oa[nt][3] * i1);
    }
}

// ---------------- MoE routing ----------------
__global__ void zero_k() {
    if (threadIdx.x < EE) { g_cnt[threadIdx.x] = 0; g_cur[threadIdx.x] = 0; }
}

__global__ void route1_k(const float* __restrict__ x, const float* __restrict__ gw) {
    int n = blockIdx.x;
    float part[EE];
#pragma unroll
    for (int e = 0; e < EE; e++) part[e] = 0.f;
    for (int d = threadIdx.x; d < D_; d += 256) {
        float xv = x[(size_t)n * D_ + d];
#pragma unroll
        for (int e = 0; e < EE; e++) part[e] = fmaf(xv, gw[e * D_ + d], part[e]);
    }
    __shared__ float red[256];
    __shared__ float lg[EE];
    for (int e = 0; e < EE; e++) {
        red[threadIdx.x] = part[e]; __syncthreads();
        for (int st = 128; st > 0; st >>= 1) {
            if (threadIdx.x < st) red[threadIdx.x] += red[threadIdx.x + st];
            __syncthreads();
        }
        if (threadIdx.x == 0) lg[e] = red[0];
        __syncthreads();
    }
    if (threadIdx.x == 0) {
        int i0 = 0; float b0 = lg[0];
        for (int e = 1; e < EE; e++) if (lg[e] > b0) { b0 = lg[e]; i0 = e; }
        int i1 = -1; float b1 = -1e30f;
        for (int e = 0; e < EE; e++) { if (e == i0) continue; if (lg[e] > b1) { b1 = lg[e]; i1 = e; } }
        float m = fmaxf(b0, b1);
        float w0 = __expf(b0 - m), w1 = __expf(b1 - m);
        float s = w0 + w1; w0 /= s; w1 /= s;
        g_tope[n*2] = i0; g_tope[n*2+1] = i1;
        g_topw[n*2] = w0; g_topw[n*2+1] = w1;
        atomicAdd(&g_cnt[i0], 1); atomicAdd(&g_cnt[i1], 1);
    }
}

__global__ void scan_k() {
    int o = 0;
    for (int e = 0; e < EE; e++) { g_off[e] = o; o += g_cnt[e]; }
}

__global__ void assign_k() {
    int n = blockIdx.x * 256 + threadIdx.x;
    if (n >= NTOK) return;
#pragma unroll
    for (int kk = 0; kk < 2; kk++) {
        int e = g_tope[n*2 + kk];
        int p = g_off[e] + atomicAdd(&g_cur[e], 1);
        g_slot_tok[p] = n;
        g_slot_w[p]   = g_topw[n*2 + kk];
        g_tok_pos[n*2 + kk] = p;
    }
}

__global__ void swiglu_k() {
    int i = blockIdx.x * 256 + threadIdx.x;
    if (i >= NSLOT * DE_) return;
    float g = g_gb[i], u = g_ub[i];
    float sig = 1.f / (1.f + __expf(-g));
    g_gb[i] = g * sig * u;
}

__global__ void final_k(float* __restrict__ out) {
    int n = blockIdx.x;
    int p0 = g_tok_pos[n*2], p1 = g_tok_pos[n*2 + 1];
    float w0 = g_slot_w[p0], w1 = g_slot_w[p1];
    size_t hb = (size_t)n * D_;
    for (int d = threadIdx.x * 4; d < D_; d += 1024) {
        float4 hv = *(const float4*)(g_h + hb + d);
        float4 a  = *(const float4*)(g_op + (size_t)p0 * D_ + d);
        float4 b4 = *(const float4*)(g_op + (size_t)p1 * D_ + d);
        float4 o;
        o.x = hv.x + w0 * a.x + w1 * b4.x;
        o.y = hv.y + w0 * a.y + w1 * b4.y;
        o.z = hv.z + w0 * a.z + w1 * b4.z;
        o.w = hv.w + w0 * a.w + w1 * b4.w;
        *(float4*)(out + hb + d) = o;
    }
}

// ---------------- launcher ----------------
extern "C" void kernel_launch(void* const* d_in, const int* in_sizes, int n_in,
                              void* d_out, int out_size) {
    const float* hidden = (const float*)d_in[0];
    const float* ln1    = (const float*)d_in[1];
    const float* ln2    = (const float*)d_in[2];
    const float* qw     = (const float*)d_in[3];
    const float* kw     = (const float*)d_in[4];
    const float* vw     = (const float*)d_in[5];
    const float* ow     = (const float*)d_in[6];
    const float* gw     = (const float*)d_in[7];
    const float* egw    = (const float*)d_in[8];
    const float* euw    = (const float*)d_in[9];
    const float* edw    = (const float*)d_in[10];
    const int*   pos    = (const int*)d_in[11];
    float* out = (float*)d_out;

    float *xn, *qb, *kb, *vb, *ab, *hb, *x2, *gb, *ub, *op;
    cudaGetSymbolAddress((void**)&xn, g_xn);
    cudaGetSymbolAddress((void**)&qb, g_q);
    cudaGetSymbolAddress((void**)&kb, g_k);
    cudaGetSymbolAddress((void**)&vb, g_v);
    cudaGetSymbolAddress((void**)&ab, g_attn);
    cudaGetSymbolAddress((void**)&hb, g_h);
    cudaGetSymbolAddress((void**)&x2, g_xn2);
    cudaGetSymbolAddress((void**)&gb, g_gb);
    cudaGetSymbolAddress((void**)&ub, g_ub);
    cudaGetSymbolAddress((void**)&op, g_op);

    // 1. pre-attention RMSNorm
    rmsnorm_k<<<NTOK, 256>>>(hidden, ln1, xn);

    // 2. QKV projections (mma.sync bf16x3 + ldmatrix)
    dim3 gdense(D_ / TN, NTOK / TM, 1);
    gemm_mma<0><<<gdense, 256>>>(xn, qw, qb, nullptr, NTOK, D_, D_, 0);
    gemm_mma<0><<<gdense, 256>>>(xn, kw, kb, nullptr, NTOK, D_, D_, 0);
    gemm_mma<0><<<gdense, 256>>>(xn, vw, vb, nullptr, NTOK, D_, D_, 0);

    // 3. fused RoPE + Q/K split, V split/transpose
    rope_split_k<<<(NTOK * HN * 64) / 256, 256>>>(pos);
    splitv_k<<<dim3(SQ / 32, HD / 32, BB * HN), dim3(32, 8)>>>();

    // 4. mma flash attention
    attn_mma_k<<<dim3(SQ / 64, HN, BB), 128>>>(ab);

    // 5. O projection + residual
    gemm_mma<0><<<gdense, 256>>>(ab, ow, hb, hidden, NTOK, D_, D_, 0);

    // 6. post-attention RMSNorm
    rmsnorm_k<<<NTOK, 256>>>(hb, ln2, x2);

    // 7. routing
    zero_k<<<1, 32>>>();
    route1_k<<<NTOK, 256>>>(x2, gw);
    scan_k<<<1, 1>>>();
    assign_k<<<NTOK / 256, 256>>>();

    // 8. MoE expert GEMMs (mma.sync bf16x3, gathered rows)
    gemm_mma<1><<<dim3((DE_ + TN - 1) / TN, 16, EE), 256>>>(
        x2, egw, gb, nullptr, 0, DE_, D_, (long)DE_ * D_);
    gemm_mma<1><<<dim3((DE_ + TN - 1) / TN, 16, EE), 256>>>(
        x2, euw, ub, nullptr, 0, DE_, D_, (long)DE_ * D_);
    swiglu_k<<<(NSLOT * DE_ + 255) / 256, 256>>>();
    gemm_mma<2><<<dim3(D_ / TN, 16, EE), 256>>>(
        gb, edw, op, nullptr, 0, D_, DE_, (long)D_ * DE_);

    // 9. weighted combine + residual
    final_k<<<NTOK, 256>>>(out);
}

// round 13
// speedup vs baseline: 1.6686x; 1.2365x over previous
#include <cuda_runtime.h>
#include <cuda_bf16.h>
#include <math.h>
#include <stdint.h>

// ---------------- problem constants ----------------
#define BB 2
#define SQ 1024
#define D_ 2048
#define HN 16
#define HD 128
#define NTOK (BB*SQ)       // 2048
#define EE 8
#define DE_ 704
#define NSLOT (NTOK*2)     // 4096 (top-2 per token)

typedef __nv_bfloat16 bf16;

// ---------------- scratch (device globals: no allocations allowed) ----------------
__device__ float g_q   [NTOK*D_];
__device__ float g_k   [NTOK*D_];
__device__ float g_v   [NTOK*D_];
__device__ float g_attn[NTOK*D_];
__device__ float g_h   [NTOK*D_];
__device__ float g_xn  [NTOK*D_];
__device__ float g_xn2 [NTOK*D_];
__device__ float g_gb  [NSLOT*DE_];
__device__ float g_ub  [NSLOT*DE_];
__device__ float g_op  [NSLOT*D_];
__device__ int   g_cnt [EE];
__device__ int   g_cur [EE];
__device__ int   g_off [EE];
__device__ int   g_tope[NTOK*2];
__device__ float g_topw[NTOK*2];
__device__ int   g_slot_tok[NSLOT];
__device__ float g_slot_w  [NSLOT];
__device__ int   g_tok_pos [NTOK*2];
// bf16 hi/lo planes for attention
__device__ bf16 g_qh[NTOK*D_], g_ql[NTOK*D_];
__device__ bf16 g_kh[NTOK*D_], g_kl[NTOK*D_];
__device__ bf16 g_vth[NTOK*D_], g_vtl[NTOK*D_];   // V transposed [bh][HD][SQ]

// ---------------- helpers ----------------
__device__ __forceinline__ uint32_t smem_u32(const void* p) {
    uint32_t a;
    asm("{ .reg .u64 t; cvta.to.shared.u64 t, %1; cvt.u32.u64 %0, t; }" : "=r"(a) : "l"(p));
    return a;
}
__device__ __forceinline__ void mma_bf16(float* c, const uint32_t* a,
                                         uint32_t b0, uint32_t b1) {
    asm volatile(
        "mma.sync.aligned.m16n8k16.row.col.f32.bf16.bf16.f32 "
        "{%0,%1,%2,%3}, {%4,%5,%6,%7}, {%8,%9}, {%0,%1,%2,%3};"
        : "+f"(c[0]), "+f"(c[1]), "+f"(c[2]), "+f"(c[3])
        : "r"(a[0]), "r"(a[1]), "r"(a[2]), "r"(a[3]), "r"(b0), "r"(b1));
}
__device__ __forceinline__ void ldsm4(uint32_t& r0, uint32_t& r1, uint32_t& r2,
                                      uint32_t& r3, uint32_t addr) {
    asm volatile("ldmatrix.sync.aligned.m8n8.x4.shared.b16 {%0,%1,%2,%3}, [%4];"
                 : "=r"(r0), "=r"(r1), "=r"(r2), "=r"(r3) : "r"(addr));
}
__device__ __forceinline__ void split2(float x0, float x1, uint32_t& wh, uint32_t& wl) {
    bf16 h0 = __float2bfloat16(x0);
    bf16 h1 = __float2bfloat16(x1);
    bf16 l0 = __float2bfloat16(x0 - __bfloat162float(h0));
    bf16 l1 = __float2bfloat16(x1 - __bfloat162float(h1));
    wh = ((uint32_t)__bfloat16_as_ushort(h1) << 16) | __bfloat16_as_ushort(h0);
    wl = ((uint32_t)__bfloat16_as_ushort(l1) << 16) | __bfloat16_as_ushort(l0);
}
__device__ __forceinline__ void split1(float x, bf16& h, bf16& l) {
    h = __float2bfloat16(x);
    l = __float2bfloat16(x - __bfloat162float(h));
}
__device__ __forceinline__ void cpa16(uint32_t dst, const void* src) {
    asm volatile("cp.async.ca.shared.global [%0], [%1], 16;"
                 :: "r"(dst), "l"(src));
}
#define CP_COMMIT() asm volatile("cp.async.commit_group;" ::: "memory")
#define CP_WAIT0()  asm volatile("cp.async.wait_group 0;" ::: "memory")

// ---------------- tensor-core (mma.sync bf16x3, ldmatrix) GEMM ----------------
// C[M,N] = A[M,K] * W[N,K]^T (+add), fp32 in, split in kernel.
// MODE 0: dense. MODE 1: A rows gathered via g_slot_tok. MODE 2: A rows contiguous slots.
// FUSE 0: none. FUSE 1: QKV (blockIdx.x/16 selects W/C). FUSE 2: gate+up (x>=6 -> W2/C2).
#define TM 128
#define TN 128
#define BK 16
#define RS 12   // row stride in 32-bit words (48B) -> conflict-free for LDS & ldmatrix

template<int MODE, int FUSE = 0>
__global__ void __launch_bounds__(256) gemm_mma(
    const float* __restrict__ A, const float* __restrict__ W,
    float* __restrict__ C, const float* __restrict__ addp,
    int M, int Nn, int Kk, long wstride,
    const float* __restrict__ W2, float* __restrict__ C2,
    const float* __restrict__ W3, float* __restrict__ C3)
{
    __shared__ uint32_t Ah[2][TM][RS];
    __shared__ uint32_t Al[2][TM][RS];
    __shared__ uint32_t Bh[2][TN][RS];
    __shared__ uint32_t Bl[2][TN][RS];

    int e = blockIdx.z;
    int Mloc = M, base = 0;
    int bx = blockIdx.x;
    const float* Wb = W;
    float* Cp = C;
    if (FUSE == 1) {
        int sel = bx >> 4; bx &= 15;
        Wb = (sel == 0) ? W : ((sel == 1) ? W2 : W3);
        Cp = (sel == 0) ? C : ((sel == 1) ? C2 : C3);
    }
    if (FUSE == 2) {
        if (bx >= 6) { bx -= 6; Wb = W2; Cp = C2; }
    }
    const float* Wp = Wb;
    if (MODE != 0) { Mloc = g_cnt[e]; base = g_off[e]; Wp = Wb + (size_t)e * (size_t)wstride; }
    int m0 = blockIdx.y * TM;
    if (m0 >= Mloc) return;
    int n0 = bx * TN;
    int tid = threadIdx.x;

    const float* aP[2]; const float* bP[2];
    int rowL[2], c4L[2];
    bool aV[2], bV[2];
#pragma unroll
    for (int i = 0; i < 2; i++) {
        int v = tid + i * 256;
        int row = v >> 2, c4 = v & 3;
        rowL[i] = row; c4L[i] = c4;
        int gm = m0 + row;
        bool av = gm < Mloc;
        int arow;
        if (MODE == 0)      arow = av ? gm : 0;
        else if (MODE == 1) arow = av ? g_slot_tok[base + gm] : 0;
        else                arow = av ? (base + gm) : 0;
        aV[i] = av;
        aP[i] = A + (size_t)arow * Kk + c4 * 4;
        int gn = n0 + row;
        bV[i] = gn < Nn;
        bP[i] = Wp + (size_t)(bV[i] ? gn : 0) * Kk + c4 * 4;
    }

    int lane = tid & 31, g = lane >> 2, tg = lane & 3;
    int wm = (tid >> 5) & 3;
    int wn = tid >> 7;
    int mbase = wm * 32, nbase = wn * 64;

    uint32_t sAh = smem_u32(Ah), sAl = smem_u32(Al);
    uint32_t sBh = smem_u32(Bh), sBl = smem_u32(Bl);
    uint32_t aoff[2], boff[4];
#pragma unroll
    for (int mt = 0; mt < 2; mt++)
        aoff[mt] = (uint32_t)((mbase + mt * 16 + (lane & 7) + ((lane >> 3) & 1) * 8) * 48
                              + ((lane >> 4) & 1) * 16);
#pragma unroll
    for (int p = 0; p < 4; p++)
        boff[p] = (uint32_t)((nbase + p * 16 + (lane & 7) + ((lane >> 4) & 1) * 8) * 48
                             + ((lane >> 3) & 1) * 16);

    float acc[2][8][4];
#pragma unroll
    for (int mt = 0; mt < 2; mt++)
#pragma unroll
        for (int nt = 0; nt < 8; nt++)
#pragma unroll
            for (int q = 0; q < 4; q++) acc[mt][nt][q] = 0.f;

    int nk = Kk / BK;
    float4 ra[2], rb[2];
#pragma unroll
    for (int i = 0; i < 2; i++) {
        ra[i] = aV[i] ? *(const float4*)(aP[i]) : make_float4(0,0,0,0);
        rb[i] = bV[i] ? *(const float4*)(bP[i]) : make_float4(0,0,0,0);
    }

    int buf = 0;
    for (int it = 0; it < nk; it++) {
#pragma unroll
        for (int i = 0; i < 2; i++) {
            int r = rowL[i], w0 = c4L[i] * 2;
            uint32_t h0, l0, h1, l1;
            split2(ra[i].x, ra[i].y, h0, l0);
            split2(ra[i].z, ra[i].w, h1, l1);
            Ah[buf][r][w0] = h0; Ah[buf][r][w0+1] = h1;
            Al[buf][r][w0] = l0; Al[buf][r][w0+1] = l1;
            split2(rb[i].x, rb[i].y, h0, l0);
            split2(rb[i].z, rb[i].w, h1, l1);
            Bh[buf][r][w0] = h0; Bh[buf][r][w0+1] = h1;
            Bl[buf][r][w0] = l0; Bl[buf][r][w0+1] = l1;
        }
        if (it + 1 < nk) {
            int k0 = (it + 1) * BK;
#pragma unroll
            for (int i = 0; i < 2; i++) {
                ra[i] = aV[i] ? *(const float4*)(aP[i] + k0) : make_float4(0,0,0,0);
                rb[i] = bV[i] ? *(const float4*)(bP[i] + k0) : make_float4(0,0,0,0);
            }
        }
        __syncthreads();

        uint32_t bufo = (uint32_t)buf * (TM * RS * 4);
        uint32_t ah[2][4], al[2][4];
#pragma unroll
        for (int mt = 0; mt < 2; mt++) {
            ldsm4(ah[mt][0], ah[mt][1], ah[mt][2], ah[mt][3], sAh + bufo + aoff[mt]);
            ldsm4(al[mt][0], al[mt][1], al[mt][2], al[mt][3], sAl + bufo + aoff[mt]);
        }
#pragma unroll
        for (int p = 0; p < 4; p++) {
            uint32_t b00, b01, b10, b11, c00, c01, c10, c11;
            ldsm4(b00, b01, b10, b11, sBh + bufo + boff[p]);
            ldsm4(c00, c01, c10, c11, sBl + bufo + boff[p]);
#pragma unroll
            for (int mt = 0; mt < 2; mt++) {
                mma_bf16(acc[mt][2*p],   ah[mt], b00, b01);
                mma_bf16(acc[mt][2*p],   ah[mt], c00, c01);
                mma_bf16(acc[mt][2*p],   al[mt], b00, b01);
                mma_bf16(acc[mt][2*p+1], ah[mt], b10, b11);
                mma_bf16(acc[mt][2*p+1], ah[mt], c10, c11);
                mma_bf16(acc[mt][2*p+1], al[mt], b10, b11);
            }
        }
        buf ^= 1;
    }

    // epilogue: c0/c1 -> (row g, cols 2tg,2tg+1), c2/c3 -> row g+8
#pragma unroll
    for (int mt = 0; mt < 2; mt++) {
#pragma unroll
        for (int nt = 0; nt < 8; nt++) {
            int gc = n0 + nbase + nt * 8 + tg * 2;
            if (gc >= Nn) continue;
            int gm0 = m0 + mbase + mt * 16 + g;
#pragma unroll
            for (int hrow = 0; hrow < 2; hrow++) {
                int gm = gm0 + hrow * 8;
                if (gm >= Mloc) continue;
                int crow = (MODE == 0) ? gm : (base + gm);
                size_t off = (size_t)crow * Nn + gc;
                float2 vv = make_float2(acc[mt][nt][hrow * 2], acc[mt][nt][hrow * 2 + 1]);
                if (MODE == 0 && addp) {
                    float2 rv = *(const float2*)(addp + off);
                    vv.x += rv.x; vv.y += rv.y;
                }
                *(float2*)(Cp + off) = vv;
            }
        }
    }
}

// ---------------- RMSNorm ----------------
__global__ void rmsnorm_k(const float* __restrict__ x, const float* __restrict__ w,
                          float* __restrict__ o) {
    int n = blockIdx.x;
    const float* xr = x + (size_t)n * D_;
    float s = 0.f;
    for (int d = threadIdx.x; d < D_; d += 256) { float v = xr[d]; s += v * v; }
    __shared__ float red[256];
    red[threadIdx.x] = s; __syncthreads();
    for (int st = 128; st > 0; st >>= 1) {
        if (threadIdx.x < st) red[threadIdx.x] += red[threadIdx.x + st];
        __syncthreads();
    }
    float inv = rsqrtf(red[0] / (float)D_ + 1e-6f);
    float* orow = o + (size_t)n * D_;
    for (int d = threadIdx.x; d < D_; d += 256) orow[d] = xr[d] * inv * w[d];
}

// ---------------- fused RoPE + bf16 hi/lo split for Q,K ----------------
__global__ void rope_split_k(const int* __restrict__ pos) {
    int idx = blockIdx.x * 256 + threadIdx.x;
    if (idx >= NTOK * HN * 64) return;
    int j  = idx & 63;
    int hh = (idx >> 6) & 15;
    int t  = idx >> 10;
    float p = (float)pos[t];
    float inv = expf(-((float)(2 * j) / 128.0f) * 9.210340371976184f);
    float fr = p * inv;
    float sn, cs;
    sincosf(fr, &sn, &cs);
    size_t base = (size_t)t * D_ + hh * HD + j;
    bf16 h, l;
    float x1 = g_q[base], x2 = g_q[base + 64];
    float r1 = x1 * cs - x2 * sn, r2 = x2 * cs + x1 * sn;
    split1(r1, h, l); g_qh[base] = h;      g_ql[base] = l;
    split1(r2, h, l); g_qh[base + 64] = h; g_ql[base + 64] = l;
    x1 = g_k[base]; x2 = g_k[base + 64];
    r1 = x1 * cs - x2 * sn; r2 = x2 * cs + x1 * sn;
    split1(r1, h, l); g_kh[base] = h;      g_kl[base] = l;
    split1(r2, h, l); g_kh[base + 64] = h; g_kl[base + 64] = l;
}

// ---------------- split V + transpose to [bh][dim][seq] bf16 hi/lo ----------------
__global__ void splitv_k() {
    __shared__ bf16 sh[32][33], sl[32][33];
    int tx = threadIdx.x, ty = threadIdx.y;      // (32, 8)
    int s0 = blockIdx.x * 32;
    int d0 = blockIdx.y * 32;
    int bh = blockIdx.z;
    int b = bh >> 4, hh = bh & 15;
#pragma unroll
    for (int i = 0; i < 4; i++) {
        int sr = ty + i * 8;
        float v = g_v[((size_t)(b * SQ + s0 + sr)) * D_ + hh * HD + d0 + tx];
        bf16 h, l;
        split1(v, h, l);
        sh[sr][tx] = h; sl[sr][tx] = l;
    }
    __syncthreads();
#pragma unroll
    for (int i = 0; i < 4; i++) {
        int dr = ty + i * 8;
        size_t o = ((size_t)bh * HD + d0 + dr) * SQ + s0 + tx;
        g_vth[o] = sh[tx][dr];
        g_vtl[o] = sl[tx][dr];
    }
}

// ---------------- flash attention: smem-staged K/V + mma.sync bf16x3 ----------------
// grid (SQ/64, HN, BB), block 128 (4 warps x 16 q-rows). Uniform per-block kv loop;
// K/V tiles staged cooperatively via cp.async, fragments via ldmatrix (GEMM-verified
// layout: rows at 48B stride, 16 bf16 data + 16B pad).
// smem: Kh @0 [8ks][32tok][48B], Kl @12288, Vh @24576 [2ks2][128dim][48B], Vl @36864.
__global__ void __launch_bounds__(128) attn_mma_k(float* __restrict__ O)
{
    __shared__ __align__(16) uint8_t sm[49152];
    uint32_t sb = smem_u32(sm);
    int tid = threadIdx.x;
    int w = tid >> 5, lane = tid & 31;
    int g = lane >> 2, tg = lane & 3;
    int hh = blockIdx.y, b = blockIdx.z;
    int qsb = blockIdx.x * 64;
    int qs0 = qsb + w * 16;
    int bh = b * HN + hh;

    // Q fragments (hi/lo), rows g and g+8
    uint32_t qfh[8][4], qfl[8][4];
    size_t qr0 = ((size_t)(b * SQ + qs0 + g)) * D_ + hh * HD;
    size_t qr1 = qr0 + (size_t)8 * D_;
#pragma unroll
    for (int ks = 0; ks < 8; ks++) {
        int c0 = ks * 16 + 2 * tg;
        qfh[ks][0] = *(const uint32_t*)&g_qh[qr0 + c0];
        qfh[ks][1] = *(const uint32_t*)&g_qh[qr1 + c0];
        qfh[ks][2] = *(const uint32_t*)&g_qh[qr0 + c0 + 8];
        qfh[ks][3] = *(const uint32_t*)&g_qh[qr1 + c0 + 8];
        qfl[ks][0] = *(const uint32_t*)&g_ql[qr0 + c0];
        qfl[ks][1] = *(const uint32_t*)&g_ql[qr1 + c0];
        qfl[ks][2] = *(const uint32_t*)&g_ql[qr0 + c0 + 8];
        qfl[ks][3] = *(const uint32_t*)&g_ql[qr1 + c0 + 8];
    }

    uint32_t lm_row = (lane & 7) + ((lane >> 4) & 1) * 8;   // ldmatrix row pattern
    uint32_t lm_col = ((lane >> 3) & 1) * 16;               // ldmatrix 16B col half

    float m0 = -1e30f, m1 = -1e30f, l0 = 0.f, l1 = 0.f;
    float Oa[16][4];
#pragma unroll
    for (int nt = 0; nt < 16; nt++)
#pragma unroll
        for (int q = 0; q < 4; q++) Oa[nt][q] = 0.f;

    const float SC = 0.08838834764831845f;   // 1/sqrt(128)
    int row0 = qs0 + g, row1 = row0 + 8;
    int nsteps = qsb / 32 + 2;               // covers tokens < qsb+64

    for (int step = 0; step < nsteps; step++) {
        int kt = step * 32;

        // ---- cooperative stage of K/V tiles (hi+lo) ----
        {
            size_t kg = ((size_t)(b * SQ + kt)) * D_ + hh * HD;
#pragma unroll
            for (int i = 0; i < 4; i++) {
                int idx = tid * 4 + i;                    // 0..511
                int tok = idx >> 4, ks = (idx >> 1) & 7, c = idx & 1;
                size_t so = kg + (size_t)tok * D_ + ks * 16 + c * 8;
                uint32_t dst = sb + (uint32_t)(ks * 1536 + tok * 48 + c * 16);
                cpa16(dst,         g_kh + so);
                cpa16(dst + 12288, g_kl + so);
            }
            size_t vg = (size_t)bh * HD * SQ + kt;
#pragma unroll
            for (int i = 0; i < 4; i++) {
                int idx = tid * 4 + i;                    // 0..511
                int dim = idx >> 2, ks2 = (idx >> 1) & 1, c = idx & 1;
                size_t so = vg + (size_t)dim * SQ + ks2 * 16 + c * 8;
                uint32_t dst = sb + 24576u + (uint32_t)(ks2 * 6144 + dim * 48 + c * 16);
                cpa16(dst,         g_vth + so);
                cpa16(dst + 12288, g_vtl + so);
            }
        }
        CP_COMMIT();
        CP_WAIT0();
        __syncthreads();

        // ---- S = Q K^T (16x32) ----
        float s[4][4];
#pragma unroll
        for (int nt = 0; nt < 4; nt++)
#pragma unroll
            for (int q = 0; q < 4; q++) s[nt][q] = 0.f;

#pragma unroll
        for (int ks = 0; ks < 8; ks++) {
#pragma unroll
            for (int p = 0; p < 2; p++) {
                uint32_t ka = sb + (uint32_t)(ks * 1536 + (p * 16 + lm_row) * 48) + lm_col;
                uint32_t b00, b01, b10, b11, c00, c01, c10, c11;
                ldsm4(b00, b01, b10, b11, ka);
                ldsm4(c00, c01, c10, c11, ka + 12288);
                mma_bf16(s[2*p],   qfh[ks], b00, b01);
                mma_bf16(s[2*p],   qfh[ks], c00, c01);
                mma_bf16(s[2*p],   qfl[ks], b00, b01);
                mma_bf16(s[2*p+1], qfh[ks], b10, b11);
                mma_bf16(s[2*p+1], qfh[ks], c10, c11);
                mma_bf16(s[2*p+1], qfl[ks], b10, b11);
            }
        }

        // ---- scale + causal mask ----
#pragma unroll
        for (int nt = 0; nt < 4; nt++) {
            int col = kt + nt * 8 + 2 * tg;
            s[nt][0] = (col     <= row0) ? s[nt][0] * SC : -1e30f;
            s[nt][1] = (col + 1 <= row0) ? s[nt][1] * SC : -1e30f;
            s[nt][2] = (col     <= row1) ? s[nt][2] * SC : -1e30f;
            s[nt][3] = (col + 1 <= row1) ? s[nt][3] * SC : -1e30f;
        }

        // ---- online softmax ----
        float mx0 = -1e30f, mx1 = -1e30f;
#pragma unroll
        for (int nt = 0; nt < 4; nt++) {
            mx0 = fmaxf(mx0, fmaxf(s[nt][0], s[nt][1]));
            mx1 = fmaxf(mx1, fmaxf(s[nt][2], s[nt][3]));
        }
        mx0 = fmaxf(mx0, __shfl_xor_sync(0xffffffff, mx0, 1));
        mx0 = fmaxf(mx0, __shfl_xor_sync(0xffffffff, mx0, 2));
        mx1 = fmaxf(mx1, __shfl_xor_sync(0xffffffff, mx1, 1));
        mx1 = fmaxf(mx1, __shfl_xor_sync(0xffffffff, mx1, 2));
        float mn0 = fmaxf(m0, mx0), mn1 = fmaxf(m1, mx1);
        float a0 = __expf(m0 - mn0), a1 = __expf(m1 - mn1);
        float sum0 = 0.f, sum1 = 0.f;
#pragma unroll
        for (int nt = 0; nt < 4; nt++) {
            s[nt][0] = __expf(s[nt][0] - mn0);
            s[nt][1] = __expf(s[nt][1] - mn0);
            s[nt][2] = __expf(s[nt][2] - mn1);
            s[nt][3] = __expf(s[nt][3] - mn1);
            sum0 += s[nt][0] + s[nt][1];
            sum1 += s[nt][2] + s[nt][3];
        }
        sum0 += __shfl_xor_sync(0xffffffff, sum0, 1);
        sum0 += __shfl_xor_sync(0xffffffff, sum0, 2);
        sum1 += __shfl_xor_sync(0xffffffff, sum1, 1);
        sum1 += __shfl_xor_sync(0xffffffff, sum1, 2);
        l0 = l0 * a0 + sum0; l1 = l1 * a1 + sum1;
        m0 = mn0; m1 = mn1;

#pragma unroll
        for (int nt = 0; nt < 16; nt++) {
            Oa[nt][0] *= a0; Oa[nt][1] *= a0;
            Oa[nt][2] *= a1; Oa[nt][3] *= a1;
        }

        // ---- pack P fragments (hi/lo) ----
        uint32_t pah[2][4], pal[2][4];
#pragma unroll
        for (int ks2 = 0; ks2 < 2; ks2++) {
            int na = ks2 * 2, nb = na + 1;
            split2(s[na][0], s[na][1], pah[ks2][0], pal[ks2][0]);
            split2(s[na][2], s[na][3], pah[ks2][1], pal[ks2][1]);
            split2(s[nb][0], s[nb][1], pah[ks2][2], pal[ks2][2]);
            split2(s[nb][2], s[nb][3], pah[ks2][3], pal[ks2][3]);
        }

        // ---- O += P V ----
#pragma unroll
        for (int ks2 = 0; ks2 < 2; ks2++) {
#pragma unroll
            for (int p = 0; p < 8; p++) {
                uint32_t va = sb + 24576u
                            + (uint32_t)(ks2 * 6144 + (p * 16 + lm_row) * 48) + lm_col;
                uint32_t v00, v01, v10, v11, u00, u01, u10, u11;
                ldsm4(v00, v01, v10, v11, va);
                ldsm4(u00, u01, u10, u11, va + 12288);
                mma_bf16(Oa[2*p],   pah[ks2], v00, v01);
                mma_bf16(Oa[2*p],   pah[ks2], u00, u01);
                mma_bf16(Oa[2*p],   pal[ks2], v00, v01);
                mma_bf16(Oa[2*p+1], pah[ks2], v10, v11);
                mma_bf16(Oa[2*p+1], pah[ks2], u10, u11);
                mma_bf16(Oa[2*p+1], pal[ks2], v10, v11);
            }
        }
        __syncthreads();   // protect smem before next stage overwrites
    }

    float i0 = 1.f / l0, i1 = 1.f / l1;
    size_t or0 = ((size_t)(b * SQ + qs0 + g)) * D_ + hh * HD;
    size_t or1 = or0 + (size_t)8 * D_;
#pragma unroll
    for (int nt = 0; nt < 16; nt++) {
        int col = nt * 8 + 2 * tg;
        *(float2*)&O[or0 + col] = make_float2(Oa[nt][0] * i0, Oa[nt][1] * i0);
        *(float2*)&O[or1 + col] = make_float2(Oa[nt][2] * i1, Oa[nt][3] * i1);
    }
}

// ---------------- MoE routing ----------------
__global__ void zero_k() {
    if (threadIdx.x < EE) { g_cnt[threadIdx.x] = 0; g_cur[threadIdx.x] = 0; }
}

__global__ void route1_k(const float* __restrict__ x, const float* __restrict__ gw) {
    int n = blockIdx.x;
    float part[EE];
#pragma unroll
    for (int e = 0; e < EE; e++) part[e] = 0.f;
    for (int d = threadIdx.x; d < D_; d += 256) {
        float xv = x[(size_t)n * D_ + d];
#pragma unroll
        for (int e = 0; e < EE; e++) part[e] = fmaf(xv, gw[e * D_ + d], part[e]);
    }
    __shared__ float red[256];
    __shared__ float lg[EE];
    for (int e = 0; e < EE; e++) {
        red[threadIdx.x] = part[e]; __syncthreads();
        for (int st = 128; st > 0; st >>= 1) {
            if (threadIdx.x < st) red[threadIdx.x] += red[threadIdx.x + st];
            __syncthreads();
        }
        if (threadIdx.x == 0) lg[e] = red[0];
        __syncthreads();
    }
    if (threadIdx.x == 0) {
        int i0 = 0; float b0 = lg[0];
        for (int e = 1; e < EE; e++) if (lg[e] > b0) { b0 = lg[e]; i0 = e; }
        int i1 = -1; float b1 = -1e30f;
        for (int e = 0; e < EE; e++) { if (e == i0) continue; if (lg[e] > b1) { b1 = lg[e]; i1 = e; } }
        float m = fmaxf(b0, b1);
        float w0 = __expf(b0 - m), w1 = __expf(b1 - m);
        float s = w0 + w1; w0 /= s; w1 /= s;
        g_tope[n*2] = i0; g_tope[n*2+1] = i1;
        g_topw[n*2] = w0; g_topw[n*2+1] = w1;
        atomicAdd(&g_cnt[i0], 1); atomicAdd(&g_cnt[i1], 1);
    }
}

__global__ void scan_k() {
    int o = 0;
    for (int e = 0; e < EE; e++) { g_off[e] = o; o += g_cnt[e]; }
}

__global__ void assign_k() {
    int n = blockIdx.x * 256 + threadIdx.x;
    if (n >= NTOK) return;
#pragma unroll
    for (int kk = 0; kk < 2; kk++) {
        int e = g_tope[n*2 + kk];
        int p = g_off[e] + atomicAdd(&g_cur[e], 1);
        g_slot_tok[p] = n;
        g_slot_w[p]   = g_topw[n*2 + kk];
        g_tok_pos[n*2 + kk] = p;
    }
}

__global__ void swiglu_k() {
    int i = blockIdx.x * 256 + threadIdx.x;
    if (i >= NSLOT * DE_) return;
    float g = g_gb[i], u = g_ub[i];
    float sig = 1.f / (1.f + __expf(-g));
    g_gb[i] = g * sig * u;
}

__global__ void final_k(float* __restrict__ out) {
    int n = blockIdx.x;
    int p0 = g_tok_pos[n*2], p1 = g_tok_pos[n*2 + 1];
    float w0 = g_slot_w[p0], w1 = g_slot_w[p1];
    size_t hb = (size_t)n * D_;
    for (int d = threadIdx.x * 4; d < D_; d += 1024) {
        float4 hv = *(const float4*)(g_h + hb + d);
        float4 a  = *(const float4*)(g_op + (size_t)p0 * D_ + d);
        float4 b4 = *(const float4*)(g_op + (size_t)p1 * D_ + d);
        float4 o;
        o.x = hv.x + w0 * a.x + w1 * b4.x;
        o.y = hv.y + w0 * a.y + w1 * b4.y;
        o.z = hv.z + w0 * a.z + w1 * b4.z;
        o.w = hv.w + w0 * a.w + w1 * b4.w;
        *(float4*)(out + hb + d) = o;
    }
}

// ---------------- launcher ----------------
extern "C" void kernel_launch(void* const* d_in, const int* in_sizes, int n_in,
                              void* d_out, int out_size) {
    const float* hidden = (const float*)d_in[0];
    const float* ln1    = (const float*)d_in[1];
    const float* ln2    = (const float*)d_in[2];
    const float* qw     = (const float*)d_in[3];
    const float* kw     = (const float*)d_in[4];
    const float* vw     = (const float*)d_in[5];
    const float* ow     = (const float*)d_in[6];
    const float* gw     = (const float*)d_in[7];
    const float* egw    = (const float*)d_in[8];
    const float* euw    = (const float*)d_in[9];
    const float* edw    = (const float*)d_in[10];
    const int*   pos    = (const int*)d_in[11];
    float* out = (float*)d_out;

    float *xn, *qb, *kb, *vb, *ab, *hb, *x2, *gb, *ub, *op;
    cudaGetSymbolAddress((void**)&xn, g_xn);
    cudaGetSymbolAddress((void**)&qb, g_q);
    cudaGetSymbolAddress((void**)&kb, g_k);
    cudaGetSymbolAddress((void**)&vb, g_v);
    cudaGetSymbolAddress((void**)&ab, g_attn);
    cudaGetSymbolAddress((void**)&hb, g_h);
    cudaGetSymbolAddress((void**)&x2, g_xn2);
    cudaGetSymbolAddress((void**)&gb, g_gb);
    cudaGetSymbolAddress((void**)&ub, g_ub);
    cudaGetSymbolAddress((void**)&op, g_op);

    // 1. pre-attention RMSNorm
    rmsnorm_k<<<NTOK, 256>>>(hidden, ln1, xn);

    // 2. fused QKV projection (one launch, blockIdx.x/16 selects q/k/v)
    gemm_mma<0, 1><<<dim3(48, NTOK / TM, 1), 256>>>(
        xn, qw, qb, nullptr, NTOK, D_, D_, 0, kw, kb, vw, vb);

    // 3. fused RoPE + Q/K split, V split/transpose
    rope_split_k<<<(NTOK * HN * 64) / 256, 256>>>(pos);
    splitv_k<<<dim3(SQ / 32, HD / 32, BB * HN), dim3(32, 8)>>>();

    // 4. smem-staged mma flash attention
    attn_mma_k<<<dim3(SQ / 64, HN, BB), 128>>>(ab);

    // 5. O projection + residual
    gemm_mma<0><<<dim3(D_ / TN, NTOK / TM, 1), 256>>>(
        ab, ow, hb, hidden, NTOK, D_, D_, 0, nullptr, nullptr, nullptr, nullptr);

    // 6. post-attention RMSNorm
    rmsnorm_k<<<NTOK, 256>>>(hb, ln2, x2);

    // 7. routing
    zero_k<<<1, 32>>>();
    route1_k<<<NTOK, 256>>>(x2, gw);
    scan_k<<<1, 1>>>();
    assign_k<<<NTOK / 256, 256>>>();

    // 8. MoE expert GEMMs: fused gate+up, then down
    gemm_mma<1, 2><<<dim3(12, 16, EE), 256>>>(
        x2, egw, gb, nullptr, 0, DE_, D_, (long)DE_ * D_, euw, ub, nullptr, nullptr);
    swiglu_k<<<(NSLOT * DE_ + 255) / 256, 256>>>();
    gemm_mma<2><<<dim3(D_ / TN, 16, EE), 256>>>(
        gb, edw, op, nullptr, 0, D_, DE_, (long)D_ * DE_, nullptr, nullptr, nullptr, nullptr);

    // 9. weighted combine + residual
    final_k<<<NTOK, 256>>>(out);
}